// round 11
// baseline (speedup 1.0000x reference)
#include <cuda_runtime.h>
#include <cuda_fp16.h>
#include <math.h>

#define T_TOK 4096
#define C_DIM 256
#define C3    768
#define FF    1024
#define HEADS 8
#define HD    32
#define EPS   1e-5f
#define KVS   4

// ---------------- scratch (device globals; no allocation) ----------------
__device__ __half g_tok0h[T_TOK * C_DIM];
__device__ float  g_tok  [T_TOK * C_DIM];
__device__ __half g_yh   [T_TOK * C_DIM];
__device__ float  g_y32  [T_TOK * C_DIM];
__device__ __half g_qkvh [T_TOK * C3];
__device__ __half g_ovh  [T_TOK * C_DIM];
__device__ float  g_tok2 [T_TOK * C_DIM];
__device__ __half g_zh   [T_TOK * C_DIM];
__device__ __half g_h1h  [T_TOK * FF];
__device__ __half g_tok3h[T_TOK * C_DIM];
__device__ float  g_tmp  [T_TOK * C_DIM];
__device__ float  g_opart[KVS * T_TOK * C_DIM];
__device__ float  g_l    [KVS * T_TOK * HEADS];
__device__ __half g_w_in_h [C_DIM * C_DIM];
__device__ __half g_w_qkv_h[C3 * C_DIM];
__device__ __half g_w_ap_h [C_DIM * C_DIM];
__device__ __half g_w_ff1_h[FF * C_DIM];
__device__ __half g_w_ff2_h[C_DIM * FF];
__device__ __half g_w_out_h[C_DIM * C_DIM];

// ---------------- helpers ----------------
__device__ __forceinline__ unsigned pack_h2(float lo, float hi) {
    __half2 t = __floats2half2_rn(lo, hi);
    return *reinterpret_cast<unsigned*>(&t);
}
__device__ __forceinline__ unsigned ex2_h2(unsigned x) {
    unsigned y;
    asm("ex2.approx.f16x2 %0, %1;" : "=r"(y) : "r"(x));
    return y;
}
__device__ __forceinline__ void mma_f16(float c[4], const unsigned a[4], const unsigned b[2]) {
    asm volatile(
        "mma.sync.aligned.m16n8k16.row.col.f32.f16.f16.f32 "
        "{%0,%1,%2,%3}, {%4,%5,%6,%7}, {%8,%9}, {%0,%1,%2,%3};"
        : "+f"(c[0]), "+f"(c[1]), "+f"(c[2]), "+f"(c[3])
        : "r"(a[0]), "r"(a[1]), "r"(a[2]), "r"(a[3]), "r"(b[0]), "r"(b[1]));
}
__device__ __forceinline__ void ldsm4(unsigned& r0, unsigned& r1, unsigned& r2, unsigned& r3,
                                      const void* p) {
    unsigned a = (unsigned)__cvta_generic_to_shared(p);
    asm volatile("ldmatrix.sync.aligned.m8n8.x4.shared.b16 {%0,%1,%2,%3}, [%4];"
                 : "=r"(r0), "=r"(r1), "=r"(r2), "=r"(r3) : "r"(a));
}
__device__ __forceinline__ void ldsm4t(unsigned& r0, unsigned& r1, unsigned& r2, unsigned& r3,
                                       const void* p) {
    unsigned a = (unsigned)__cvta_generic_to_shared(p);
    asm volatile("ldmatrix.sync.aligned.m8n8.x4.trans.shared.b16 {%0,%1,%2,%3}, [%4];"
                 : "=r"(r0), "=r"(r1), "=r"(r2), "=r"(r3) : "r"(a));
}
__device__ __forceinline__ void cp16(void* s, const void* g) {
    unsigned sa = (unsigned)__cvta_generic_to_shared(s);
    asm volatile("cp.async.cg.shared.global [%0], [%1], 16;\n" :: "r"(sa), "l"(g));
}
#define CP_COMMIT() asm volatile("cp.async.commit_group;\n" ::: "memory")
#define CP_WAIT2()  asm volatile("cp.async.wait_group 2;\n" ::: "memory")
#define CP_WAIT1()  asm volatile("cp.async.wait_group 1;\n" ::: "memory")
#define CP_WAIT0()  asm volatile("cp.async.wait_group 0;\n" ::: "memory")
__device__ __forceinline__ void cp_wait_dyn(int rem) {
    if (rem >= 2) CP_WAIT2();
    else if (rem == 1) CP_WAIT1();
    else CP_WAIT0();
}

// ---------------- fused weight conversion f32 -> f16 (one launch) ------------
struct CvtArgs {
    const float* src[6];
    __half* dst[6];
    int n4[6];
};
__global__ void cvt_all_k(CvtArgs a) {
#pragma unroll
    for (int s = 0; s < 6; s++) {
        const float4* sp = reinterpret_cast<const float4*>(a.src[s]);
        unsigned* dp = reinterpret_cast<unsigned*>(a.dst[s]);
        int n = a.n4[s];
        for (int i = blockIdx.x * blockDim.x + threadIdx.x; i < n; i += gridDim.x * blockDim.x) {
            float4 v = sp[i];
            dp[i * 2 + 0] = pack_h2(v.x, v.y);
            dp[i * 2 + 1] = pack_h2(v.z, v.w);
        }
    }
}

// ---------------- BN (folded) + transpose -> f16 tokens ----------------
__global__ void bn_transpose_k(const float* __restrict__ x,
                               const float* __restrict__ gamma,
                               const float* __restrict__ beta,
                               const float* __restrict__ mean,
                               const float* __restrict__ var,
                               __half* __restrict__ tok0) {
    __shared__ float sm[32][33];
    int c0 = blockIdx.x * 32, t0 = blockIdx.y * 32;
    int tx = threadIdx.x, ty = threadIdx.y;
    int c = c0 + ty;
    float a  = gamma[c] * rsqrtf(var[c] + EPS);
    float bb = beta[c] - mean[c] * a;
    sm[ty][tx] = x[c * T_TOK + t0 + tx] * a + bb;
    __syncthreads();
    tok0[(t0 + ty) * C_DIM + c0 + tx] = __float2half(sm[tx][ty]);
}

// ---------------- transpose back + image residual ----------------
__global__ void out_transpose_k(const float* __restrict__ tmp,
                                const float* __restrict__ xin,
                                float* __restrict__ out) {
    __shared__ float sm[32][33];
    int c0 = blockIdx.x * 32, t0 = blockIdx.y * 32;
    int tx = threadIdx.x, ty = threadIdx.y;
    sm[ty][tx] = tmp[(t0 + ty) * C_DIM + c0 + tx];
    __syncthreads();
    int c = c0 + ty, t = t0 + tx;
    out[c * T_TOK + t] = sm[tx][ty] + xin[c * T_TOK + t];
}

// ---------------- LayerNorm: 2 rows/warp, vectorized ----------------
__global__ void ln_k(const float* __restrict__ x,
                     const float* __restrict__ g,
                     const float* __restrict__ b,
                     __half* __restrict__ yh, float* __restrict__ y32) {
    int warp = threadIdx.x >> 5, lane = threadIdx.x & 31;
    int row0 = blockIdx.x * 16 + warp * 2;
    const float4* xa = reinterpret_cast<const float4*>(x + (size_t)row0 * C_DIM) + lane * 2;
    const float4* xb = reinterpret_cast<const float4*>(x + (size_t)(row0 + 1) * C_DIM) + lane * 2;
    float4 a0 = xa[0], a1 = xa[1], b0v = xb[0], b1v = xb[1];
    float va[8] = { a0.x, a0.y, a0.z, a0.w, a1.x, a1.y, a1.z, a1.w };
    float vb[8] = { b0v.x, b0v.y, b0v.z, b0v.w, b1v.x, b1v.y, b1v.z, b1v.w };
    float sA = 0.f, s2A = 0.f, sB = 0.f, s2B = 0.f;
#pragma unroll
    for (int i = 0; i < 8; i++) {
        sA += va[i]; s2A += va[i] * va[i];
        sB += vb[i]; s2B += vb[i] * vb[i];
    }
#pragma unroll
    for (int off = 16; off > 0; off >>= 1) {
        sA  += __shfl_xor_sync(0xffffffffu, sA,  off);
        s2A += __shfl_xor_sync(0xffffffffu, s2A, off);
        sB  += __shfl_xor_sync(0xffffffffu, sB,  off);
        s2B += __shfl_xor_sync(0xffffffffu, s2B, off);
    }
    float muA = sA * (1.f / C_DIM), muB = sB * (1.f / C_DIM);
    float rA = rsqrtf(s2A * (1.f / C_DIM) - muA * muA + EPS);
    float rB = rsqrtf(s2B * (1.f / C_DIM) - muB * muB + EPS);
    const float4* gp = reinterpret_cast<const float4*>(g) + lane * 2;
    const float4* bp = reinterpret_cast<const float4*>(b) + lane * 2;
    float4 g0 = gp[0], g1 = gp[1], bb0 = bp[0], bb1 = bp[1];
    float gg[8] = { g0.x, g0.y, g0.z, g0.w, g1.x, g1.y, g1.z, g1.w };
    float bb[8] = { bb0.x, bb0.y, bb0.z, bb0.w, bb1.x, bb1.y, bb1.z, bb1.w };
    float oA[8], oB[8];
#pragma unroll
    for (int i = 0; i < 8; i++) {
        oA[i] = (va[i] - muA) * rA * gg[i] + bb[i];
        oB[i] = (vb[i] - muB) * rB * gg[i] + bb[i];
    }
    uint4 hA, hB;
    hA.x = pack_h2(oA[0], oA[1]); hA.y = pack_h2(oA[2], oA[3]);
    hA.z = pack_h2(oA[4], oA[5]); hA.w = pack_h2(oA[6], oA[7]);
    hB.x = pack_h2(oB[0], oB[1]); hB.y = pack_h2(oB[2], oB[3]);
    hB.z = pack_h2(oB[4], oB[5]); hB.w = pack_h2(oB[6], oB[7]);
    *reinterpret_cast<uint4*>(yh + (size_t)row0 * C_DIM + lane * 8) = hA;
    *reinterpret_cast<uint4*>(yh + (size_t)(row0 + 1) * C_DIM + lane * 8) = hB;
    if (y32) {
        float4* ya = reinterpret_cast<float4*>(y32 + (size_t)row0 * C_DIM) + lane * 2;
        float4* yb = reinterpret_cast<float4*>(y32 + (size_t)(row0 + 1) * C_DIM) + lane * 2;
        ya[0] = make_float4(oA[0], oA[1], oA[2], oA[3]);
        ya[1] = make_float4(oA[4], oA[5], oA[6], oA[7]);
        yb[0] = make_float4(oB[0], oB[1], oB[2], oB[3]);
        yb[1] = make_float4(oB[4], oB[5], oB[6], oB[7]);
    }
}

// ---------------- fp16 GEMM, BM=64 BN=64 BK=32, 4-stage ring, LDSM ----------
// 256 threads (8 warps, 4x2 grid, warp tile 16x32).
#define GROW 40
#define GSTAGE (128 * GROW)                 // halves per stage (A 64 + W 64 rows)
#define SMEM_GEMM (4 * GSTAGE * 2)          // bytes = 40KB
__global__ __launch_bounds__(256, 2)
void gemm_k(const __half* __restrict__ A, const __half* __restrict__ W,
            const float* __restrict__ bias,
            const float* __restrict__ add1, const float* __restrict__ add2,
            float* __restrict__ outf, __half* __restrict__ outh,
            int M, int N, int K, int act) {
    extern __shared__ __half smh[];
    const int tid = threadIdx.x;
    const int warp = tid >> 5, l = tid & 31;
    const int wm = warp >> 1, wn = warp & 1;
    const int r = l >> 2, c2 = (l & 3) * 2;
    const int sub = l & 7, gq = l >> 3;
    const int m0 = blockIdx.y * 64, n0 = blockIdx.x * 64;
    const int lrow = tid >> 2, lch = (tid & 3) * 8;

    float acc[4][4];
#pragma unroll
    for (int j = 0; j < 4; j++)
#pragma unroll
        for (int i = 0; i < 4; i++) acc[j][i] = 0.f;

    const int nt = K >> 5;
#pragma unroll
    for (int t0 = 0; t0 < 3; t0++) {
        if (t0 < nt) {
            __half* As = smh + t0 * GSTAGE;
            __half* Ws = As + 64 * GROW;
            cp16(&As[lrow * GROW + lch], A + (size_t)(m0 + lrow) * K + t0 * 32 + lch);
            cp16(&Ws[lrow * GROW + lch], W + (size_t)(n0 + lrow) * K + t0 * 32 + lch);
            CP_COMMIT();
        }
    }

    for (int t = 0; t < nt; t++) {
        cp_wait_dyn(nt - t - 1);
        __syncthreads();
        __half* As = smh + (t & 3) * GSTAGE;
        __half* Ws = As + 64 * GROW;
#pragma unroll
        for (int kk = 0; kk < 2; kk++) {
            unsigned au[4], bu[4][2];
            const __half* pa = &As[(wm * 16 + (gq & 1) * 8 + sub) * GROW
                                   + kk * 16 + (gq >> 1) * 8];
            ldsm4(au[0], au[1], au[2], au[3], pa);
#pragma unroll
            for (int jp = 0; jp < 2; jp++) {
                const __half* pb = &Ws[(wn * 32 + jp * 16 + (gq >> 1) * 8 + sub) * GROW
                                       + kk * 16 + (gq & 1) * 8];
                ldsm4(bu[2 * jp][0], bu[2 * jp][1], bu[2 * jp + 1][0], bu[2 * jp + 1][1], pb);
            }
#pragma unroll
            for (int j = 0; j < 4; j++)
                mma_f16(acc[j], au, bu[j]);
        }
        if (t + 3 < nt) {
            __half* Asn = smh + ((t + 3) & 3) * GSTAGE;
            __half* Wsn = Asn + 64 * GROW;
            int k0 = (t + 3) * 32;
            cp16(&Asn[lrow * GROW + lch], A + (size_t)(m0 + lrow) * K + k0 + lch);
            cp16(&Wsn[lrow * GROW + lch], W + (size_t)(n0 + lrow) * K + k0 + lch);
            CP_COMMIT();
        }
    }

    // epilogue (f32)
#pragma unroll
    for (int j = 0; j < 4; j++) {
        int rr0 = m0 + wm * 16 + r;
        int cc = n0 + wn * 32 + 8 * j + c2;
#pragma unroll
        for (int half = 0; half < 2; half++) {
            int rr = rr0 + half * 8;
            float v0 = acc[j][half * 2 + 0] + bias[cc];
            float v1 = acc[j][half * 2 + 1] + bias[cc + 1];
            size_t idx = (size_t)rr * N + cc;
            if (add1) { v0 += add1[idx]; v1 += add1[idx + 1]; }
            if (add2) { v0 += add2[idx]; v1 += add2[idx + 1]; }
            if (act == 1) {
                v0 = 0.5f * v0 * (1.0f + erff(v0 * 0.70710678118654752f));
                v1 = 0.5f * v1 * (1.0f + erff(v1 * 0.70710678118654752f));
            }
            if (outf) { outf[idx] = v0; outf[idx + 1] = v1; }
            if (outh) *reinterpret_cast<unsigned*>(outh + idx) = pack_h2(v0, v1);
        }
    }
}

// ---------------- flash attention: 4-stage cp.async K/V ring (unchanged) ----
#define AROW 40
#define AKV  (64 * AROW)
#define SMEM_ATTN ((128 * AROW + 4 * 2 * AKV) * 2)
__global__ __launch_bounds__(256)
void attn_k(const __half* __restrict__ qkv,
            float* __restrict__ opart, float* __restrict__ lpart) {
    extern __shared__ __half sma[];
    __half* Qb = sma;
    __half* KV = sma + 128 * AROW;

    const int h = blockIdx.y, q0 = blockIdx.x * 128, split = blockIdx.z;
    const int tid = threadIdx.x;
    const int w = tid >> 5, l = tid & 31;
    const int r = l >> 2, c2 = (l & 3) * 2;
    const int sub = l & 7, gq = l >> 3;
    const float K2 = 1.4426950408889634f * 0.17677669529663689f;
    const __half2 K2h = __float2half2_rn(K2);
    const int lrow = tid >> 2, lch = (tid & 3) * 8;

#pragma unroll
    for (int i = 0; i < 2; i++) {
        int s = tid + i * 256;
        int row = s >> 2, ch = (s & 3) * 8;
        uint4 v = *reinterpret_cast<const uint4*>(qkv + (size_t)(q0 + row) * C3 + h * HD + ch);
        __half2* hv = reinterpret_cast<__half2*>(&v);
#pragma unroll
        for (int k = 0; k < 4; k++) hv[k] = __hmul2(hv[k], K2h);
        *reinterpret_cast<uint4*>(&Qb[row * AROW + ch]) = v;
    }

    const int NT = (T_TOK / KVS) / 64;
    const int kb0 = split * NT;
#pragma unroll
    for (int t0 = 0; t0 < 3; t0++) {
        __half* Ks = KV + t0 * 2 * AKV;
        __half* Vs = Ks + AKV;
        const __half* kp = qkv + (size_t)((kb0 + t0) * 64 + lrow) * C3 + C_DIM + h * HD + lch;
        cp16(&Ks[lrow * AROW + lch], kp);
        cp16(&Vs[lrow * AROW + lch], kp + C_DIM);
        CP_COMMIT();
    }
    __syncthreads();
    unsigned aq[2][4];
#pragma unroll
    for (int kk = 0; kk < 2; kk++) {
        const __half* pq = &Qb[(w * 16 + (gq & 1) * 8 + sub) * AROW + kk * 16 + (gq >> 1) * 8];
        ldsm4(aq[kk][0], aq[kk][1], aq[kk][2], aq[kk][3], pq);
    }

    float oa[4][4];
#pragma unroll
    for (int jd = 0; jd < 4; jd++)
#pragma unroll
        for (int i = 0; i < 4; i++) oa[jd][i] = 0.f;
    float l0 = 0.f, l1 = 0.f;

    for (int t = 0; t < NT; t++) {
        cp_wait_dyn(NT - t - 1);
        __syncthreads();
        __half* Ks = KV + (t & 3) * 2 * AKV;
        __half* Vs = Ks + AKV;

        float st[8][4];
#pragma unroll
        for (int j = 0; j < 8; j++)
#pragma unroll
            for (int i = 0; i < 4; i++) st[j][i] = 0.f;
#pragma unroll
        for (int kk = 0; kk < 2; kk++) {
            unsigned bk[8][2];
#pragma unroll
            for (int jp = 0; jp < 4; jp++) {
                const __half* pk = &Ks[(jp * 16 + (gq >> 1) * 8 + sub) * AROW
                                       + kk * 16 + (gq & 1) * 8];
                ldsm4(bk[2 * jp][0], bk[2 * jp][1], bk[2 * jp + 1][0], bk[2 * jp + 1][1], pk);
            }
#pragma unroll
            for (int j = 0; j < 8; j++)
                mma_f16(st[j], aq[kk], bk[j]);
        }
        unsigned pa[8], pb[8];
#pragma unroll
        for (int j = 0; j < 8; j++) {
            pa[j] = ex2_h2(pack_h2(st[j][0], st[j][1]));
            pb[j] = ex2_h2(pack_h2(st[j][2], st[j][3]));
        }
        {
            __half2 sa = *reinterpret_cast<__half2*>(&pa[0]);
            __half2 sb = *reinterpret_cast<__half2*>(&pb[0]);
#pragma unroll
            for (int j = 1; j < 8; j++) {
                sa = __hadd2(sa, *reinterpret_cast<__half2*>(&pa[j]));
                sb = __hadd2(sb, *reinterpret_cast<__half2*>(&pb[j]));
            }
            float2 fa = __half22float2(sa), fb = __half22float2(sb);
            l0 += fa.x + fa.y;
            l1 += fb.x + fb.y;
        }
#pragma unroll
        for (int kk = 0; kk < 4; kk++) {
            unsigned bv[4][2];
#pragma unroll
            for (int jp = 0; jp < 2; jp++) {
                const __half* pv = &Vs[(kk * 16 + (gq & 1) * 8 + sub) * AROW
                                       + jp * 16 + (gq >> 1) * 8];
                ldsm4t(bv[2 * jp][0], bv[2 * jp][1], bv[2 * jp + 1][0], bv[2 * jp + 1][1], pv);
            }
            unsigned ap[4] = { pa[2 * kk], pb[2 * kk], pa[2 * kk + 1], pb[2 * kk + 1] };
#pragma unroll
            for (int jd = 0; jd < 4; jd++)
                mma_f16(oa[jd], ap, bv[jd]);
        }
        if (t + 3 < NT) {
            __half* Ksn = KV + ((t + 3) & 3) * 2 * AKV;
            __half* Vsn = Ksn + AKV;
            const __half* kp = qkv + (size_t)((kb0 + t + 3) * 64 + lrow) * C3 + C_DIM + h * HD + lch;
            cp16(&Ksn[lrow * AROW + lch], kp);
            cp16(&Vsn[lrow * AROW + lch], kp + C_DIM);
            CP_COMMIT();
        }
    }

    l0 += __shfl_xor_sync(0xffffffffu, l0, 1);
    l0 += __shfl_xor_sync(0xffffffffu, l0, 2);
    l1 += __shfl_xor_sync(0xffffffffu, l1, 1);
    l1 += __shfl_xor_sync(0xffffffffu, l1, 2);

    int row0 = q0 + w * 16 + r;
    float* ob = opart + ((size_t)split * T_TOK) * C_DIM;
#pragma unroll
    for (int jd = 0; jd < 4; jd++) {
        int col = h * HD + 8 * jd + c2;
        *reinterpret_cast<float2*>(ob + (size_t)row0 * C_DIM + col) =
            make_float2(oa[jd][0], oa[jd][1]);
        *reinterpret_cast<float2*>(ob + (size_t)(row0 + 8) * C_DIM + col) =
            make_float2(oa[jd][2], oa[jd][3]);
    }
    if ((l & 3) == 0) {
        lpart[((size_t)split * T_TOK + row0) * HEADS + h] = l0;
        lpart[((size_t)split * T_TOK + row0 + 8) * HEADS + h] = l1;
    }
}

// ---------------- combine KV splits -> f16 (vectorized) ----------------
__global__ void attn_combine_k(const float* __restrict__ opart,
                               const float* __restrict__ lpart,
                               __half* __restrict__ ov) {
    int row  = blockIdx.x * 8 + (threadIdx.x >> 5);
    int lane = threadIdx.x & 31;
    int head = lane >> 2;
    int c = lane * 8;
    float lsum = 0.f;
#pragma unroll
    for (int s = 0; s < KVS; s++)
        lsum += lpart[((size_t)s * T_TOK + row) * HEADS + head];
    float o[8] = {0.f, 0.f, 0.f, 0.f, 0.f, 0.f, 0.f, 0.f};
#pragma unroll
    for (int s = 0; s < KVS; s++) {
        const float4* op = reinterpret_cast<const float4*>(
            opart + ((size_t)s * T_TOK + row) * C_DIM + c);
        float4 p0 = op[0], p1 = op[1];
        o[0] += p0.x; o[1] += p0.y; o[2] += p0.z; o[3] += p0.w;
        o[4] += p1.x; o[5] += p1.y; o[6] += p1.z; o[7] += p1.w;
    }
    float inv = 1.f / lsum;
    uint4 ho;
    ho.x = pack_h2(o[0] * inv, o[1] * inv); ho.y = pack_h2(o[2] * inv, o[3] * inv);
    ho.z = pack_h2(o[4] * inv, o[5] * inv); ho.w = pack_h2(o[6] * inv, o[7] * inv);
    *reinterpret_cast<uint4*>(ov + (size_t)row * C_DIM + c) = ho;
}

// ---------------- launch ----------------
template <typename Sym>
static void* dev_ptr(const Sym& sym) {
    void* p = nullptr;
    cudaGetSymbolAddress(&p, sym);
    return p;
}

extern "C" void kernel_launch(void* const* d_in, const int* in_sizes, int n_in,
                              void* d_out, int out_size) {
    (void)in_sizes; (void)n_in; (void)out_size;
    const float* x        = (const float*)d_in[0];
    const float* bn_gamma = (const float*)d_in[1];
    const float* bn_beta  = (const float*)d_in[2];
    const float* bn_mean  = (const float*)d_in[3];
    const float* bn_var   = (const float*)d_in[4];
    const float* w_in     = (const float*)d_in[5];
    const float* b_in     = (const float*)d_in[6];
    const float* ln1_g    = (const float*)d_in[7];
    const float* ln1_b    = (const float*)d_in[8];
    const float* w_qkv    = (const float*)d_in[9];
    const float* b_qkv    = (const float*)d_in[10];
    const float* w_ap     = (const float*)d_in[11];
    const float* b_ap     = (const float*)d_in[12];
    const float* ln2_g    = (const float*)d_in[13];
    const float* ln2_b    = (const float*)d_in[14];
    const float* w_ff1    = (const float*)d_in[15];
    const float* b_ff1    = (const float*)d_in[16];
    const float* w_ff2    = (const float*)d_in[17];
    const float* b_ff2    = (const float*)d_in[18];
    const float* w_out    = (const float*)d_in[19];
    const float* b_out    = (const float*)d_in[20];
    float* out = (float*)d_out;

    __half* tok0h = (__half*)dev_ptr(g_tok0h);
    float*  tok   = (float*)dev_ptr(g_tok);
    __half* yh    = (__half*)dev_ptr(g_yh);
    float*  y32   = (float*)dev_ptr(g_y32);
    __half* qkvh  = (__half*)dev_ptr(g_qkvh);
    __half* ovh   = (__half*)dev_ptr(g_ovh);
    float*  tok2  = (float*)dev_ptr(g_tok2);
    __half* zh    = (__half*)dev_ptr(g_zh);
    __half* h1h   = (__half*)dev_ptr(g_h1h);
    __half* tok3h = (__half*)dev_ptr(g_tok3h);
    float*  tmp   = (float*)dev_ptr(g_tmp);
    float*  opart = (float*)dev_ptr(g_opart);
    float*  lpart = (float*)dev_ptr(g_l);
    __half* w_in_h  = (__half*)dev_ptr(g_w_in_h);
    __half* w_qkv_h = (__half*)dev_ptr(g_w_qkv_h);
    __half* w_ap_h  = (__half*)dev_ptr(g_w_ap_h);
    __half* w_ff1_h = (__half*)dev_ptr(g_w_ff1_h);
    __half* w_ff2_h = (__half*)dev_ptr(g_w_ff2_h);
    __half* w_out_h = (__half*)dev_ptr(g_w_out_h);

    static bool attr_set = false;
    if (!attr_set) {
        cudaFuncSetAttribute(gemm_k, cudaFuncAttributeMaxDynamicSharedMemorySize, SMEM_GEMM);
        cudaFuncSetAttribute(attn_k, cudaFuncAttributeMaxDynamicSharedMemorySize, SMEM_ATTN);
        attr_set = true;
    }

    // fused weight conversion
    CvtArgs ca;
    ca.src[0] = w_in;  ca.dst[0] = w_in_h;  ca.n4[0] = C_DIM * C_DIM / 4;
    ca.src[1] = w_qkv; ca.dst[1] = w_qkv_h; ca.n4[1] = C3 * C_DIM / 4;
    ca.src[2] = w_ap;  ca.dst[2] = w_ap_h;  ca.n4[2] = C_DIM * C_DIM / 4;
    ca.src[3] = w_ff1; ca.dst[3] = w_ff1_h; ca.n4[3] = FF * C_DIM / 4;
    ca.src[4] = w_ff2; ca.dst[4] = w_ff2_h; ca.n4[4] = C_DIM * FF / 4;
    ca.src[5] = w_out; ca.dst[5] = w_out_h; ca.n4[5] = C_DIM * C_DIM / 4;
    cvt_all_k<<<448, 256>>>(ca);

    // 1) BN + transpose
    bn_transpose_k<<<dim3(C_DIM / 32, T_TOK / 32), dim3(32, 32)>>>(
        x, bn_gamma, bn_beta, bn_mean, bn_var, tok0h);
    // 2) proj_in -> tok (f32)
    gemm_k<<<dim3(C_DIM / 64, T_TOK / 64), 256, SMEM_GEMM>>>(
        tok0h, w_in_h, b_in, nullptr, nullptr, tok, nullptr, T_TOK, C_DIM, C_DIM, 0);
    // 3) LN1 -> yh + y32
    ln_k<<<T_TOK / 16, 256>>>(tok, ln1_g, ln1_b, yh, y32);
    // 4) QKV -> qkvh (f16)
    gemm_k<<<dim3(C3 / 64, T_TOK / 64), 256, SMEM_GEMM>>>(
        yh, w_qkv_h, b_qkv, nullptr, nullptr, nullptr, qkvh, T_TOK, C3, C_DIM, 0);
    // 5) attention + combine
    attn_k<<<dim3(T_TOK / 128, HEADS, KVS), 256, SMEM_ATTN>>>(qkvh, opart, lpart);
    attn_combine_k<<<T_TOK / 8, 256>>>(opart, lpart, ovh);
    // 6) attn proj + y32 + tok -> tok2 (f32)
    gemm_k<<<dim3(C_DIM / 64, T_TOK / 64), 256, SMEM_GEMM>>>(
        ovh, w_ap_h, b_ap, y32, tok, tok2, nullptr, T_TOK, C_DIM, C_DIM, 0);
    // 7) LN2 -> zh
    ln_k<<<T_TOK / 16, 256>>>(tok2, ln2_g, ln2_b, zh, nullptr);
    // 8) FF1 + gelu -> h1h (f16)
    gemm_k<<<dim3(FF / 64, T_TOK / 64), 256, SMEM_GEMM>>>(
        zh, w_ff1_h, b_ff1, nullptr, nullptr, nullptr, h1h, T_TOK, FF, C_DIM, 1);
    // 9) FF2 + tok2 -> tok3h (f16)
    gemm_k<<<dim3(C_DIM / 64, T_TOK / 64), 256, SMEM_GEMM>>>(
        h1h, w_ff2_h, b_ff2, tok2, nullptr, nullptr, tok3h, T_TOK, C_DIM, FF, 0);
    // 10) proj_out -> tmp (f32)
    gemm_k<<<dim3(C_DIM / 64, T_TOK / 64), 256, SMEM_GEMM>>>(
        tok3h, w_out_h, b_out, nullptr, nullptr, tmp, nullptr, T_TOK, C_DIM, C_DIM, 0);
    // 11) transpose back + image residual
    out_transpose_k<<<dim3(C_DIM / 32, T_TOK / 32), dim3(32, 32)>>>(tmp, x, out);
}

// round 13
// speedup vs baseline: 1.0649x; 1.0649x over previous
#include <cuda_runtime.h>
#include <cuda_fp16.h>
#include <math.h>

#define T_TOK 4096
#define C_DIM 256
#define C3    768
#define FF    1024
#define HEADS 8
#define HD    32
#define EPS   1e-5f
#define KVS   4

// ---------------- scratch (device globals; no allocation) ----------------
__device__ __half g_tok0h[T_TOK * C_DIM];
__device__ float  g_tok  [T_TOK * C_DIM];
__device__ __half g_yh   [T_TOK * C_DIM];
__device__ float  g_y32  [T_TOK * C_DIM];
__device__ __half g_qkvh [T_TOK * C3];
__device__ __half g_ovh  [T_TOK * C_DIM];
__device__ float  g_tok2 [T_TOK * C_DIM];
__device__ __half g_zh   [T_TOK * C_DIM];
__device__ __half g_h1h  [T_TOK * FF];
__device__ __half g_tok3h[T_TOK * C_DIM];
__device__ float  g_opart[KVS * T_TOK * C_DIM];
__device__ float  g_l    [KVS * T_TOK * HEADS];
__device__ __half g_w_in_h [C_DIM * C_DIM];
__device__ __half g_w_qkv_h[C3 * C_DIM];
__device__ __half g_w_ap_h [C_DIM * C_DIM];
__device__ __half g_w_ff1_h[FF * C_DIM];
__device__ __half g_w_ff2_h[C_DIM * FF];
__device__ __half g_w_out_h[C_DIM * C_DIM];

// ---------------- helpers ----------------
__device__ __forceinline__ unsigned pack_h2(float lo, float hi) {
    __half2 t = __floats2half2_rn(lo, hi);
    return *reinterpret_cast<unsigned*>(&t);
}
__device__ __forceinline__ unsigned ex2_h2(unsigned x) {
    unsigned y;
    asm("ex2.approx.f16x2 %0, %1;" : "=r"(y) : "r"(x));
    return y;
}
__device__ __forceinline__ void mma_f16(float c[4], const unsigned a[4], const unsigned b[2]) {
    asm volatile(
        "mma.sync.aligned.m16n8k16.row.col.f32.f16.f16.f32 "
        "{%0,%1,%2,%3}, {%4,%5,%6,%7}, {%8,%9}, {%0,%1,%2,%3};"
        : "+f"(c[0]), "+f"(c[1]), "+f"(c[2]), "+f"(c[3])
        : "r"(a[0]), "r"(a[1]), "r"(a[2]), "r"(a[3]), "r"(b[0]), "r"(b[1]));
}
__device__ __forceinline__ void ldsm4(unsigned& r0, unsigned& r1, unsigned& r2, unsigned& r3,
                                      const void* p) {
    unsigned a = (unsigned)__cvta_generic_to_shared(p);
    asm volatile("ldmatrix.sync.aligned.m8n8.x4.shared.b16 {%0,%1,%2,%3}, [%4];"
                 : "=r"(r0), "=r"(r1), "=r"(r2), "=r"(r3) : "r"(a));
}
__device__ __forceinline__ void ldsm4t(unsigned& r0, unsigned& r1, unsigned& r2, unsigned& r3,
                                       const void* p) {
    unsigned a = (unsigned)__cvta_generic_to_shared(p);
    asm volatile("ldmatrix.sync.aligned.m8n8.x4.trans.shared.b16 {%0,%1,%2,%3}, [%4];"
                 : "=r"(r0), "=r"(r1), "=r"(r2), "=r"(r3) : "r"(a));
}
__device__ __forceinline__ void cp16(void* s, const void* g) {
    unsigned sa = (unsigned)__cvta_generic_to_shared(s);
    asm volatile("cp.async.cg.shared.global [%0], [%1], 16;\n" :: "r"(sa), "l"(g));
}
#define CP_COMMIT() asm volatile("cp.async.commit_group;\n" ::: "memory")
#define CP_WAIT2()  asm volatile("cp.async.wait_group 2;\n" ::: "memory")
#define CP_WAIT1()  asm volatile("cp.async.wait_group 1;\n" ::: "memory")
#define CP_WAIT0()  asm volatile("cp.async.wait_group 0;\n" ::: "memory")
__device__ __forceinline__ void cp_wait_dyn(int rem) {
    if (rem >= 2) CP_WAIT2();
    else if (rem == 1) CP_WAIT1();
    else CP_WAIT0();
}

// ---------------- prep: weight cvt + BN-transpose in ONE launch --------------
struct CvtArgs {
    const float* src[6];
    __half* dst[6];
    int n4[6];
};
#define BN_BLOCKS ((C_DIM / 32) * (T_TOK / 32))   // 1024
#define CVT_BLOCKS 448
__global__ void prep_k(CvtArgs a,
                       const float* __restrict__ x,
                       const float* __restrict__ gamma,
                       const float* __restrict__ beta,
                       const float* __restrict__ mean,
                       const float* __restrict__ var,
                       __half* __restrict__ tok0) {
    __shared__ float sm[32][33];
    int bid = blockIdx.x;
    int tid = threadIdx.x;
    if (bid < BN_BLOCKS) {
        int c0 = (bid & 7) * 32, t0 = (bid >> 3) * 32;
        int tx = tid & 31, tw = tid >> 5;
#pragma unroll
        for (int i = 0; i < 4; i++) {
            int ty = tw + i * 8;
            int c = c0 + ty;
            float av = gamma[c] * rsqrtf(var[c] + EPS);
            float bv = beta[c] - mean[c] * av;
            sm[ty][tx] = x[c * T_TOK + t0 + tx] * av + bv;
        }
        __syncthreads();
#pragma unroll
        for (int i = 0; i < 4; i++) {
            int ty = tw + i * 8;
            tok0[(t0 + ty) * C_DIM + c0 + tx] = __float2half(sm[tx][ty]);
        }
    } else {
        int vb = bid - BN_BLOCKS;   // 0..447
#pragma unroll
        for (int s = 0; s < 6; s++) {
            const float4* sp = reinterpret_cast<const float4*>(a.src[s]);
            unsigned* dp = reinterpret_cast<unsigned*>(a.dst[s]);
            int n = a.n4[s];
            for (int i = vb * 256 + tid; i < n; i += CVT_BLOCKS * 256) {
                float4 v = sp[i];
                dp[i * 2 + 0] = pack_h2(v.x, v.y);
                dp[i * 2 + 1] = pack_h2(v.z, v.w);
            }
        }
    }
}

// ---------------- standard fp16 GEMM, BM=64 BN=64 BK=32, 4-stage ring -------
#define GROW 40
#define GSTAGE (128 * GROW)
#define SMEM_GEMM (4 * GSTAGE * 2)
__global__ __launch_bounds__(256, 2)
void gemm_k(const __half* __restrict__ A, const __half* __restrict__ W,
            const float* __restrict__ bias,
            const float* __restrict__ add1, const float* __restrict__ add2,
            float* __restrict__ outf, __half* __restrict__ outh,
            int M, int N, int K, int act) {
    extern __shared__ __half smh[];
    const int tid = threadIdx.x;
    const int warp = tid >> 5, l = tid & 31;
    const int wm = warp >> 1, wn = warp & 1;
    const int r = l >> 2, c2 = (l & 3) * 2;
    const int sub = l & 7, gq = l >> 3;
    const int m0 = blockIdx.y * 64, n0 = blockIdx.x * 64;
    const int lrow = tid >> 2, lch = (tid & 3) * 8;

    float acc[4][4];
#pragma unroll
    for (int j = 0; j < 4; j++)
#pragma unroll
        for (int i = 0; i < 4; i++) acc[j][i] = 0.f;

    const int nt = K >> 5;
#pragma unroll
    for (int t0 = 0; t0 < 3; t0++) {
        if (t0 < nt) {
            __half* As = smh + t0 * GSTAGE;
            __half* Ws = As + 64 * GROW;
            cp16(&As[lrow * GROW + lch], A + (size_t)(m0 + lrow) * K + t0 * 32 + lch);
            cp16(&Ws[lrow * GROW + lch], W + (size_t)(n0 + lrow) * K + t0 * 32 + lch);
            CP_COMMIT();
        }
    }

    for (int t = 0; t < nt; t++) {
        cp_wait_dyn(nt - t - 1);
        __syncthreads();
        __half* As = smh + (t & 3) * GSTAGE;
        __half* Ws = As + 64 * GROW;
#pragma unroll
        for (int kk = 0; kk < 2; kk++) {
            unsigned au[4], bu[4][2];
            const __half* pa = &As[(wm * 16 + (gq & 1) * 8 + sub) * GROW
                                   + kk * 16 + (gq >> 1) * 8];
            ldsm4(au[0], au[1], au[2], au[3], pa);
#pragma unroll
            for (int jp = 0; jp < 2; jp++) {
                const __half* pb = &Ws[(wn * 32 + jp * 16 + (gq >> 1) * 8 + sub) * GROW
                                       + kk * 16 + (gq & 1) * 8];
                ldsm4(bu[2 * jp][0], bu[2 * jp][1], bu[2 * jp + 1][0], bu[2 * jp + 1][1], pb);
            }
#pragma unroll
            for (int j = 0; j < 4; j++)
                mma_f16(acc[j], au, bu[j]);
        }
        if (t + 3 < nt) {
            __half* Asn = smh + ((t + 3) & 3) * GSTAGE;
            __half* Wsn = Asn + 64 * GROW;
            int k0 = (t + 3) * 32;
            cp16(&Asn[lrow * GROW + lch], A + (size_t)(m0 + lrow) * K + k0 + lch);
            cp16(&Wsn[lrow * GROW + lch], W + (size_t)(n0 + lrow) * K + k0 + lch);
            CP_COMMIT();
        }
    }

#pragma unroll
    for (int j = 0; j < 4; j++) {
        int rr0 = m0 + wm * 16 + r;
        int cc = n0 + wn * 32 + 8 * j + c2;
#pragma unroll
        for (int half = 0; half < 2; half++) {
            int rr = rr0 + half * 8;
            float v0 = acc[j][half * 2 + 0] + bias[cc];
            float v1 = acc[j][half * 2 + 1] + bias[cc + 1];
            size_t idx = (size_t)rr * N + cc;
            if (add1) { v0 += add1[idx]; v1 += add1[idx + 1]; }
            if (add2) { v0 += add2[idx]; v1 += add2[idx + 1]; }
            if (act == 1) {
                v0 = 0.5f * v0 * (1.0f + erff(v0 * 0.70710678118654752f));
                v1 = 0.5f * v1 * (1.0f + erff(v1 * 0.70710678118654752f));
            }
            if (outf) { outf[idx] = v0; outf[idx + 1] = v1; }
            if (outh) *reinterpret_cast<unsigned*>(outh + idx) = pack_h2(v0, v1);
        }
    }
}

// ---------------- LN-fused GEMM: BM=32, BN=256(full row), K=256 --------------
// grid M/32=128 blocks, 256 threads (8 warps: wm=warp>>2 in {0,1}, wn=warp&3).
#define LSTAGE ((32 + 256) * GROW)          // halves per stage
#define SMEM_LN (4 * LSTAGE * 2)            // 92160 bytes
__global__ __launch_bounds__(256)
void gemm_ln_k(const __half* __restrict__ A, const __half* __restrict__ W,
               const float* __restrict__ bias,
               const float* __restrict__ add1, const float* __restrict__ add2,
               const float* __restrict__ lng, const float* __restrict__ lnb,
               float* __restrict__ out_pre,
               __half* __restrict__ out_lnh, float* __restrict__ out_lnf,
               int M, int K) {
    extern __shared__ __half smh[];
    const int tid = threadIdx.x;
    const int warp = tid >> 5, l = tid & 31;
    const int wm = warp >> 2, wn = warp & 3;
    const int r = l >> 2, c2 = (l & 3) * 2;
    const int sub = l & 7, gq = l >> 3;
    const int m0 = blockIdx.x * 32;

    float acc[8][4];
#pragma unroll
    for (int j = 0; j < 8; j++)
#pragma unroll
        for (int i = 0; i < 4; i++) acc[j][i] = 0.f;

    const int nt = K >> 5;   // 8
#pragma unroll
    for (int t0 = 0; t0 < 3; t0++) {
        __half* As = smh + t0 * LSTAGE;
        __half* Ws = As + 32 * GROW;
        if (tid < 128) {
            int row = tid >> 2, ch = (tid & 3) * 8;
            cp16(&As[row * GROW + ch], A + (size_t)(m0 + row) * K + t0 * 32 + ch);
        }
#pragma unroll
        for (int i = 0; i < 4; i++) {
            int row = (tid >> 2) + i * 64, ch = (tid & 3) * 8;
            cp16(&Ws[row * GROW + ch], W + (size_t)row * K + t0 * 32 + ch);
        }
        CP_COMMIT();
    }

    for (int t = 0; t < nt; t++) {
        cp_wait_dyn(nt - t - 1);
        __syncthreads();
        __half* As = smh + (t & 3) * LSTAGE;
        __half* Ws = As + 32 * GROW;
#pragma unroll
        for (int kk = 0; kk < 2; kk++) {
            unsigned au[4], bu[8][2];
            const __half* pa = &As[(wm * 16 + (gq & 1) * 8 + sub) * GROW
                                   + kk * 16 + (gq >> 1) * 8];
            ldsm4(au[0], au[1], au[2], au[3], pa);
#pragma unroll
            for (int jp = 0; jp < 4; jp++) {
                const __half* pb = &Ws[(wn * 64 + jp * 16 + (gq >> 1) * 8 + sub) * GROW
                                       + kk * 16 + (gq & 1) * 8];
                ldsm4(bu[2 * jp][0], bu[2 * jp][1], bu[2 * jp + 1][0], bu[2 * jp + 1][1], pb);
            }
#pragma unroll
            for (int j = 0; j < 8; j++)
                mma_f16(acc[j], au, bu[j]);
        }
        if (t + 3 < nt) {
            __half* Asn = smh + ((t + 3) & 3) * LSTAGE;
            __half* Wsn = Asn + 32 * GROW;
            int k0 = (t + 3) * 32;
            if (tid < 128) {
                int row = tid >> 2, ch = (tid & 3) * 8;
                cp16(&Asn[row * GROW + ch], A + (size_t)(m0 + row) * K + k0 + ch);
            }
#pragma unroll
            for (int i = 0; i < 4; i++) {
                int row = (tid >> 2) + i * 64, ch = (tid & 3) * 8;
                cp16(&Wsn[row * GROW + ch], W + (size_t)row * K + k0 + ch);
            }
            CP_COMMIT();
        }
    }
    __syncthreads();   // ring reads done; smem reused for LN reduction

    float2* red = reinterpret_cast<float2*>(smh);   // [32 rows][4 wn]
    const int rbase = wm * 16 + r;
    float s[2] = {0.f, 0.f}, q[2] = {0.f, 0.f};
#pragma unroll
    for (int j = 0; j < 8; j++) {
        int cc = wn * 64 + 8 * j + c2;
#pragma unroll
        for (int half = 0; half < 2; half++) {
            int rg = m0 + rbase + half * 8;
            size_t idx = (size_t)rg * C_DIM + cc;
            float v0 = acc[j][half * 2 + 0] + bias[cc];
            float v1 = acc[j][half * 2 + 1] + bias[cc + 1];
            if (add1) { v0 += add1[idx]; v1 += add1[idx + 1]; }
            if (add2) { v0 += add2[idx]; v1 += add2[idx + 1]; }
            if (out_pre) *reinterpret_cast<float2*>(out_pre + idx) = make_float2(v0, v1);
            acc[j][half * 2 + 0] = v0; acc[j][half * 2 + 1] = v1;
            s[half] += v0 + v1;
            q[half] += v0 * v0 + v1 * v1;
        }
    }
#pragma unroll
    for (int off = 1; off <= 2; off <<= 1) {
        s[0] += __shfl_xor_sync(0xffffffffu, s[0], off);
        q[0] += __shfl_xor_sync(0xffffffffu, q[0], off);
        s[1] += __shfl_xor_sync(0xffffffffu, s[1], off);
        q[1] += __shfl_xor_sync(0xffffffffu, q[1], off);
    }
    if ((l & 3) == 0) {
        red[rbase * 4 + wn]       = make_float2(s[0], q[0]);
        red[(rbase + 8) * 4 + wn] = make_float2(s[1], q[1]);
    }
    __syncthreads();
    float mu[2], rs[2];
#pragma unroll
    for (int half = 0; half < 2; half++) {
        int rl = rbase + half * 8;
        float ss = 0.f, qq = 0.f;
#pragma unroll
        for (int w4 = 0; w4 < 4; w4++) {
            float2 e = red[rl * 4 + w4];
            ss += e.x; qq += e.y;
        }
        float m = ss * (1.f / C_DIM);
        mu[half] = m;
        rs[half] = rsqrtf(qq * (1.f / C_DIM) - m * m + EPS);
    }
#pragma unroll
    for (int j = 0; j < 8; j++) {
        int cc = wn * 64 + 8 * j + c2;
        float2 g2 = *reinterpret_cast<const float2*>(lng + cc);
        float2 b2 = *reinterpret_cast<const float2*>(lnb + cc);
#pragma unroll
        for (int half = 0; half < 2; half++) {
            int rg = m0 + rbase + half * 8;
            size_t idx = (size_t)rg * C_DIM + cc;
            float o0 = (acc[j][half * 2 + 0] - mu[half]) * rs[half] * g2.x + b2.x;
            float o1 = (acc[j][half * 2 + 1] - mu[half]) * rs[half] * g2.y + b2.y;
            *reinterpret_cast<unsigned*>(out_lnh + idx) = pack_h2(o0, o1);
            if (out_lnf) *reinterpret_cast<float2*>(out_lnf + idx) = make_float2(o0, o1);
        }
    }
}

// ---------------- proj_out GEMM + transposed write + image residual ----------
// Transpose tile stride = 68 floats (multiple of 4 -> float4-aligned rows).
#define TSTRIDE 68
__global__ __launch_bounds__(256, 2)
void gemm_out_k(const __half* __restrict__ A, const __half* __restrict__ W,
                const float* __restrict__ bias,
                const float* __restrict__ xin, float* __restrict__ out,
                int K) {
    extern __shared__ __half smh[];
    const int tid = threadIdx.x;
    const int warp = tid >> 5, l = tid & 31;
    const int wm = warp >> 1, wn = warp & 1;
    const int r = l >> 2, c2 = (l & 3) * 2;
    const int sub = l & 7, gq = l >> 3;
    const int m0 = blockIdx.y * 64, n0 = blockIdx.x * 64;
    const int lrow = tid >> 2, lch = (tid & 3) * 8;

    float acc[4][4];
#pragma unroll
    for (int j = 0; j < 4; j++)
#pragma unroll
        for (int i = 0; i < 4; i++) acc[j][i] = 0.f;

    const int nt = K >> 5;
#pragma unroll
    for (int t0 = 0; t0 < 3; t0++) {
        if (t0 < nt) {
            __half* As = smh + t0 * GSTAGE;
            __half* Ws = As + 64 * GROW;
            cp16(&As[lrow * GROW + lch], A + (size_t)(m0 + lrow) * K + t0 * 32 + lch);
            cp16(&Ws[lrow * GROW + lch], W + (size_t)(n0 + lrow) * K + t0 * 32 + lch);
            CP_COMMIT();
        }
    }
    for (int t = 0; t < nt; t++) {
        cp_wait_dyn(nt - t - 1);
        __syncthreads();
        __half* As = smh + (t & 3) * GSTAGE;
        __half* Ws = As + 64 * GROW;
#pragma unroll
        for (int kk = 0; kk < 2; kk++) {
            unsigned au[4], bu[4][2];
            const __half* pa = &As[(wm * 16 + (gq & 1) * 8 + sub) * GROW
                                   + kk * 16 + (gq >> 1) * 8];
            ldsm4(au[0], au[1], au[2], au[3], pa);
#pragma unroll
            for (int jp = 0; jp < 2; jp++) {
                const __half* pb = &Ws[(wn * 32 + jp * 16 + (gq >> 1) * 8 + sub) * GROW
                                       + kk * 16 + (gq & 1) * 8];
                ldsm4(bu[2 * jp][0], bu[2 * jp][1], bu[2 * jp + 1][0], bu[2 * jp + 1][1], pb);
            }
#pragma unroll
            for (int j = 0; j < 4; j++)
                mma_f16(acc[j], au, bu[j]);
        }
        if (t + 3 < nt) {
            __half* Asn = smh + ((t + 3) & 3) * GSTAGE;
            __half* Wsn = Asn + 64 * GROW;
            int k0 = (t + 3) * 32;
            cp16(&Asn[lrow * GROW + lch], A + (size_t)(m0 + lrow) * K + k0 + lch);
            cp16(&Wsn[lrow * GROW + lch], W + (size_t)(n0 + lrow) * K + k0 + lch);
            CP_COMMIT();
        }
    }
    __syncthreads();   // done with ring; reuse as f32 transpose tile [64][TSTRIDE]
    float* tsm = reinterpret_cast<float*>(smh);
#pragma unroll
    for (int j = 0; j < 4; j++) {
        int ccl = wn * 32 + 8 * j + c2;
#pragma unroll
        for (int half = 0; half < 2; half++) {
            int rrl = wm * 16 + r + half * 8;
            int cc = n0 + ccl;
            float v0 = acc[j][half * 2 + 0] + bias[cc];
            float v1 = acc[j][half * 2 + 1] + bias[cc + 1];
            tsm[ccl * TSTRIDE + rrl] = v0;
            tsm[(ccl + 1) * TSTRIDE + rrl] = v1;
        }
    }
    __syncthreads();
    {
        int row = tid >> 2;                  // local c (0..63)
        int colb = (tid & 3) * 16;           // local t base
        int c = n0 + row;
#pragma unroll
        for (int i = 0; i < 4; i++) {
            int tcol = colb + i * 4;
            float4 v = *reinterpret_cast<float4*>(&tsm[row * TSTRIDE + tcol]);
            const float4 xr = *reinterpret_cast<const float4*>(xin + (size_t)c * T_TOK + m0 + tcol);
            v.x += xr.x; v.y += xr.y; v.z += xr.z; v.w += xr.w;
            *reinterpret_cast<float4*>(out + (size_t)c * T_TOK + m0 + tcol) = v;
        }
    }
}

// ---------------- flash attention (unchanged) ----------------
#define AROW 40
#define AKV  (64 * AROW)
#define SMEM_ATTN ((128 * AROW + 4 * 2 * AKV) * 2)
__global__ __launch_bounds__(256)
void attn_k(const __half* __restrict__ qkv,
            float* __restrict__ opart, float* __restrict__ lpart) {
    extern __shared__ __half sma[];
    __half* Qb = sma;
    __half* KV = sma + 128 * AROW;

    const int h = blockIdx.y, q0 = blockIdx.x * 128, split = blockIdx.z;
    const int tid = threadIdx.x;
    const int w = tid >> 5, l = tid & 31;
    const int r = l >> 2, c2 = (l & 3) * 2;
    const int sub = l & 7, gq = l >> 3;
    const float K2 = 1.4426950408889634f * 0.17677669529663689f;
    const __half2 K2h = __float2half2_rn(K2);
    const int lrow = tid >> 2, lch = (tid & 3) * 8;

#pragma unroll
    for (int i = 0; i < 2; i++) {
        int s = tid + i * 256;
        int row = s >> 2, ch = (s & 3) * 8;
        uint4 v = *reinterpret_cast<const uint4*>(qkv + (size_t)(q0 + row) * C3 + h * HD + ch);
        __half2* hv = reinterpret_cast<__half2*>(&v);
#pragma unroll
        for (int k = 0; k < 4; k++) hv[k] = __hmul2(hv[k], K2h);
        *reinterpret_cast<uint4*>(&Qb[row * AROW + ch]) = v;
    }

    const int NT = (T_TOK / KVS) / 64;
    const int kb0 = split * NT;
#pragma unroll
    for (int t0 = 0; t0 < 3; t0++) {
        __half* Ks = KV + t0 * 2 * AKV;
        __half* Vs = Ks + AKV;
        const __half* kp = qkv + (size_t)((kb0 + t0) * 64 + lrow) * C3 + C_DIM + h * HD + lch;
        cp16(&Ks[lrow * AROW + lch], kp);
        cp16(&Vs[lrow * AROW + lch], kp + C_DIM);
        CP_COMMIT();
    }
    __syncthreads();
    unsigned aq[2][4];
#pragma unroll
    for (int kk = 0; kk < 2; kk++) {
        const __half* pq = &Qb[(w * 16 + (gq & 1) * 8 + sub) * AROW + kk * 16 + (gq >> 1) * 8];
        ldsm4(aq[kk][0], aq[kk][1], aq[kk][2], aq[kk][3], pq);
    }

    float oa[4][4];
#pragma unroll
    for (int jd = 0; jd < 4; jd++)
#pragma unroll
        for (int i = 0; i < 4; i++) oa[jd][i] = 0.f;
    float l0 = 0.f, l1 = 0.f;

    for (int t = 0; t < NT; t++) {
        cp_wait_dyn(NT - t - 1);
        __syncthreads();
        __half* Ks = KV + (t & 3) * 2 * AKV;
        __half* Vs = Ks + AKV;

        float st[8][4];
#pragma unroll
        for (int j = 0; j < 8; j++)
#pragma unroll
            for (int i = 0; i < 4; i++) st[j][i] = 0.f;
#pragma unroll
        for (int kk = 0; kk < 2; kk++) {
            unsigned bk[8][2];
#pragma unroll
            for (int jp = 0; jp < 4; jp++) {
                const __half* pk = &Ks[(jp * 16 + (gq >> 1) * 8 + sub) * AROW
                                       + kk * 16 + (gq & 1) * 8];
                ldsm4(bk[2 * jp][0], bk[2 * jp][1], bk[2 * jp + 1][0], bk[2 * jp + 1][1], pk);
            }
#pragma unroll
            for (int j = 0; j < 8; j++)
                mma_f16(st[j], aq[kk], bk[j]);
        }
        unsigned pa[8], pb[8];
#pragma unroll
        for (int j = 0; j < 8; j++) {
            pa[j] = ex2_h2(pack_h2(st[j][0], st[j][1]));
            pb[j] = ex2_h2(pack_h2(st[j][2], st[j][3]));
        }
        {
            __half2 sa = *reinterpret_cast<__half2*>(&pa[0]);
            __half2 sb = *reinterpret_cast<__half2*>(&pb[0]);
#pragma unroll
            for (int j = 1; j < 8; j++) {
                sa = __hadd2(sa, *reinterpret_cast<__half2*>(&pa[j]));
                sb = __hadd2(sb, *reinterpret_cast<__half2*>(&pb[j]));
            }
            float2 fa = __half22float2(sa), fb = __half22float2(sb);
            l0 += fa.x + fa.y;
            l1 += fb.x + fb.y;
        }
#pragma unroll
        for (int kk = 0; kk < 4; kk++) {
            unsigned bv[4][2];
#pragma unroll
            for (int jp = 0; jp < 2; jp++) {
                const __half* pv = &Vs[(kk * 16 + (gq & 1) * 8 + sub) * AROW
                                       + jp * 16 + (gq >> 1) * 8];
                ldsm4t(bv[2 * jp][0], bv[2 * jp][1], bv[2 * jp + 1][0], bv[2 * jp + 1][1], pv);
            }
            unsigned ap[4] = { pa[2 * kk], pb[2 * kk], pa[2 * kk + 1], pb[2 * kk + 1] };
#pragma unroll
            for (int jd = 0; jd < 4; jd++)
                mma_f16(oa[jd], ap, bv[jd]);
        }
        if (t + 3 < NT) {
            __half* Ksn = KV + ((t + 3) & 3) * 2 * AKV;
            __half* Vsn = Ksn + AKV;
            const __half* kp = qkv + (size_t)((kb0 + t + 3) * 64 + lrow) * C3 + C_DIM + h * HD + lch;
            cp16(&Ksn[lrow * AROW + lch], kp);
            cp16(&Vsn[lrow * AROW + lch], kp + C_DIM);
            CP_COMMIT();
        }
    }

    l0 += __shfl_xor_sync(0xffffffffu, l0, 1);
    l0 += __shfl_xor_sync(0xffffffffu, l0, 2);
    l1 += __shfl_xor_sync(0xffffffffu, l1, 1);
    l1 += __shfl_xor_sync(0xffffffffu, l1, 2);

    int row0 = q0 + w * 16 + r;
    float* ob = opart + ((size_t)split * T_TOK) * C_DIM;
#pragma unroll
    for (int jd = 0; jd < 4; jd++) {
        int col = h * HD + 8 * jd + c2;
        *reinterpret_cast<float2*>(ob + (size_t)row0 * C_DIM + col) =
            make_float2(oa[jd][0], oa[jd][1]);
        *reinterpret_cast<float2*>(ob + (size_t)(row0 + 8) * C_DIM + col) =
            make_float2(oa[jd][2], oa[jd][3]);
    }
    if ((l & 3) == 0) {
        lpart[((size_t)split * T_TOK + row0) * HEADS + h] = l0;
        lpart[((size_t)split * T_TOK + row0 + 8) * HEADS + h] = l1;
    }
}

// ---------------- combine KV splits -> f16 (vectorized) ----------------
__global__ void attn_combine_k(const float* __restrict__ opart,
                               const float* __restrict__ lpart,
                               __half* __restrict__ ov) {
    int row  = blockIdx.x * 8 + (threadIdx.x >> 5);
    int lane = threadIdx.x & 31;
    int head = lane >> 2;
    int c = lane * 8;
    float lsum = 0.f;
#pragma unroll
    for (int s = 0; s < KVS; s++)
        lsum += lpart[((size_t)s * T_TOK + row) * HEADS + head];
    float o[8] = {0.f, 0.f, 0.f, 0.f, 0.f, 0.f, 0.f, 0.f};
#pragma unroll
    for (int s = 0; s < KVS; s++) {
        const float4* op = reinterpret_cast<const float4*>(
            opart + ((size_t)s * T_TOK + row) * C_DIM + c);
        float4 p0 = op[0], p1 = op[1];
        o[0] += p0.x; o[1] += p0.y; o[2] += p0.z; o[3] += p0.w;
        o[4] += p1.x; o[5] += p1.y; o[6] += p1.z; o[7] += p1.w;
    }
    float inv = 1.f / lsum;
    uint4 ho;
    ho.x = pack_h2(o[0] * inv, o[1] * inv); ho.y = pack_h2(o[2] * inv, o[3] * inv);
    ho.z = pack_h2(o[4] * inv, o[5] * inv); ho.w = pack_h2(o[6] * inv, o[7] * inv);
    *reinterpret_cast<uint4*>(ov + (size_t)row * C_DIM + c) = ho;
}

// ---------------- launch ----------------
template <typename Sym>
static void* dev_ptr(const Sym& sym) {
    void* p = nullptr;
    cudaGetSymbolAddress(&p, sym);
    return p;
}

extern "C" void kernel_launch(void* const* d_in, const int* in_sizes, int n_in,
                              void* d_out, int out_size) {
    (void)in_sizes; (void)n_in; (void)out_size;
    const float* x        = (const float*)d_in[0];
    const float* bn_gamma = (const float*)d_in[1];
    const float* bn_beta  = (const float*)d_in[2];
    const float* bn_mean  = (const float*)d_in[3];
    const float* bn_var   = (const float*)d_in[4];
    const float* w_in     = (const float*)d_in[5];
    const float* b_in     = (const float*)d_in[6];
    const float* ln1_g    = (const float*)d_in[7];
    const float* ln1_b    = (const float*)d_in[8];
    const float* w_qkv    = (const float*)d_in[9];
    const float* b_qkv    = (const float*)d_in[10];
    const float* w_ap     = (const float*)d_in[11];
    const float* b_ap     = (const float*)d_in[12];
    const float* ln2_g    = (const float*)d_in[13];
    const float* ln2_b    = (const float*)d_in[14];
    const float* w_ff1    = (const float*)d_in[15];
    const float* b_ff1    = (const float*)d_in[16];
    const float* w_ff2    = (const float*)d_in[17];
    const float* b_ff2    = (const float*)d_in[18];
    const float* w_out    = (const float*)d_in[19];
    const float* b_out    = (const float*)d_in[20];
    float* out = (float*)d_out;

    __half* tok0h = (__half*)dev_ptr(g_tok0h);
    float*  tok   = (float*)dev_ptr(g_tok);
    __half* yh    = (__half*)dev_ptr(g_yh);
    float*  y32   = (float*)dev_ptr(g_y32);
    __half* qkvh  = (__half*)dev_ptr(g_qkvh);
    __half* ovh   = (__half*)dev_ptr(g_ovh);
    float*  tok2  = (float*)dev_ptr(g_tok2);
    __half* zh    = (__half*)dev_ptr(g_zh);
    __half* h1h   = (__half*)dev_ptr(g_h1h);
    __half* tok3h = (__half*)dev_ptr(g_tok3h);
    float*  opart = (float*)dev_ptr(g_opart);
    float*  lpart = (float*)dev_ptr(g_l);
    __half* w_in_h  = (__half*)dev_ptr(g_w_in_h);
    __half* w_qkv_h = (__half*)dev_ptr(g_w_qkv_h);
    __half* w_ap_h  = (__half*)dev_ptr(g_w_ap_h);
    __half* w_ff1_h = (__half*)dev_ptr(g_w_ff1_h);
    __half* w_ff2_h = (__half*)dev_ptr(g_w_ff2_h);
    __half* w_out_h = (__half*)dev_ptr(g_w_out_h);

    static bool attr_set = false;
    if (!attr_set) {
        cudaFuncSetAttribute(gemm_k, cudaFuncAttributeMaxDynamicSharedMemorySize, SMEM_GEMM);
        cudaFuncSetAttribute(gemm_out_k, cudaFuncAttributeMaxDynamicSharedMemorySize, SMEM_GEMM);
        cudaFuncSetAttribute(gemm_ln_k, cudaFuncAttributeMaxDynamicSharedMemorySize, SMEM_LN);
        cudaFuncSetAttribute(attn_k, cudaFuncAttributeMaxDynamicSharedMemorySize, SMEM_ATTN);
        attr_set = true;
    }

    CvtArgs ca;
    ca.src[0] = w_in;  ca.dst[0] = w_in_h;  ca.n4[0] = C_DIM * C_DIM / 4;
    ca.src[1] = w_qkv; ca.dst[1] = w_qkv_h; ca.n4[1] = C3 * C_DIM / 4;
    ca.src[2] = w_ap;  ca.dst[2] = w_ap_h;  ca.n4[2] = C_DIM * C_DIM / 4;
    ca.src[3] = w_ff1; ca.dst[3] = w_ff1_h; ca.n4[3] = FF * C_DIM / 4;
    ca.src[4] = w_ff2; ca.dst[4] = w_ff2_h; ca.n4[4] = C_DIM * FF / 4;
    ca.src[5] = w_out; ca.dst[5] = w_out_h; ca.n4[5] = C_DIM * C_DIM / 4;

    // 1) prep: weight cvt + BN transpose (one launch)
    prep_k<<<BN_BLOCKS + CVT_BLOCKS, 256>>>(ca, x, bn_gamma, bn_beta, bn_mean, bn_var, tok0h);
    // 2) proj_in + LN1 (fused)
    gemm_ln_k<<<T_TOK / 32, 256, SMEM_LN>>>(
        tok0h, w_in_h, b_in, nullptr, nullptr, ln1_g, ln1_b,
        tok, yh, y32, T_TOK, C_DIM);
    // 3) QKV
    gemm_k<<<dim3(C3 / 64, T_TOK / 64), 256, SMEM_GEMM>>>(
        yh, w_qkv_h, b_qkv, nullptr, nullptr, nullptr, qkvh, T_TOK, C3, C_DIM, 0);
    // 4) attention + 5) combine
    attn_k<<<dim3(T_TOK / 128, HEADS, KVS), 256, SMEM_ATTN>>>(qkvh, opart, lpart);
    attn_combine_k<<<T_TOK / 8, 256>>>(opart, lpart, ovh);
    // 6) attn-proj + residuals + LN2 (fused)
    gemm_ln_k<<<T_TOK / 32, 256, SMEM_LN>>>(
        ovh, w_ap_h, b_ap, y32, tok, ln2_g, ln2_b,
        tok2, zh, nullptr, T_TOK, C_DIM);
    // 7) FF1 + gelu
    gemm_k<<<dim3(FF / 64, T_TOK / 64), 256, SMEM_GEMM>>>(
        zh, w_ff1_h, b_ff1, nullptr, nullptr, nullptr, h1h, T_TOK, FF, C_DIM, 1);
    // 8) FF2 + tok2 residual
    gemm_k<<<dim3(C_DIM / 64, T_TOK / 64), 256, SMEM_GEMM>>>(
        h1h, w_ff2_h, b_ff2, tok2, nullptr, nullptr, tok3h, T_TOK, C_DIM, FF, 0);
    // 9) proj_out + transpose + image residual (fused)
    gemm_out_k<<<dim3(C_DIM / 64, T_TOK / 64), 256, SMEM_GEMM>>>(
        tok3h, w_out_h, b_out, x, out, C_DIM);
}